// round 1
// baseline (speedup 1.0000x reference)
#include <cuda_runtime.h>
#include <math.h>

#define B_    8192
#define DIN_  1024
#define H_    2048
#define DOUT_ 1024
#define E_    8

// Scratch (allocation-free): ping-pong activation buffers + gate probs.
__device__ float g_bufA[(size_t)B_ * H_];
__device__ float g_bufB[(size_t)B_ * H_];
__device__ float g_gate[(size_t)B_ * E_];

// ---------------------------------------------------------------------------
// Gate: logits = x @ Wg + bg ; gate = softmax(logits) per row. One warp/row.
// ---------------------------------------------------------------------------
__global__ void gate_kernel(const float* __restrict__ x,
                            const float* __restrict__ Wg,
                            const float* __restrict__ bg) {
    int gwarp = (blockIdx.x * blockDim.x + threadIdx.x) >> 5;
    int lane  = threadIdx.x & 31;
    if (gwarp >= B_) return;
    const float* xr = x + (size_t)gwarp * DIN_;
    float acc[E_];
#pragma unroll
    for (int e = 0; e < E_; e++) acc[e] = 0.f;
    for (int i = lane; i < DIN_; i += 32) {
        float xv = xr[i];
        const float4* w4 = reinterpret_cast<const float4*>(Wg + (size_t)i * E_);
        float4 w0 = w4[0], w1 = w4[1];
        acc[0] += xv * w0.x; acc[1] += xv * w0.y;
        acc[2] += xv * w0.z; acc[3] += xv * w0.w;
        acc[4] += xv * w1.x; acc[5] += xv * w1.y;
        acc[6] += xv * w1.z; acc[7] += xv * w1.w;
    }
#pragma unroll
    for (int e = 0; e < E_; e++) {
#pragma unroll
        for (int o = 16; o > 0; o >>= 1)
            acc[e] += __shfl_xor_sync(0xffffffffu, acc[e], o);
    }
    if (lane == 0) {
        float mx = -1e30f;
#pragma unroll
        for (int e = 0; e < E_; e++) { acc[e] += bg[e]; mx = fmaxf(mx, acc[e]); }
        float s = 0.f;
#pragma unroll
        for (int e = 0; e < E_; e++) { acc[e] = expf(acc[e] - mx); s += acc[e]; }
        float inv = 1.f / s;
#pragma unroll
        for (int e = 0; e < E_; e++) g_gate[(size_t)gwarp * E_ + e] = acc[e] * inv;
    }
}

// ---------------------------------------------------------------------------
// SGEMM 128x128 tile, BK=8, 256 threads, 8x8 microtile per thread.
// Inner product issued as packed fma.rn.f32x2 (2 FMAs/inst -> 2x FFMA rate).
// MODE 0: C = A@B + bias[col]
// MODE 1: C (+)= gate[row,expert] * (A@B + bias[col])   (isFirst -> '=')
// Assumes M%128==0, N%128==0, K%8==0 (true for all shapes here).
// ---------------------------------------------------------------------------
template <int MODE>
__global__ __launch_bounds__(256, 2)
void gemm_kernel(const float* __restrict__ A, const float* __restrict__ Bw,
                 const float* __restrict__ bias, float* __restrict__ C,
                 int M, int N, int K, int expert, int isFirst) {
    __shared__ float As[8][128];
    __shared__ float Bs[8][128];

    const int tid = threadIdx.x;
    const int tx = tid & 15;        // 16 thread columns
    const int ty = tid >> 4;        // 16 thread rows
    const int bx = blockIdx.x;      // N tile
    const int by = blockIdx.y;      // M tile

    const int arow = tid >> 1;             // 0..127
    const int acol = (tid & 1) * 4;        // 0 or 4
    const int brow = tid >> 5;             // 0..7
    const int bcol = (tid & 31) * 4;       // 0..124

    const float* Aptr = A + (size_t)(by * 128 + arow) * K + acol;
    const float* Bptr = Bw + (size_t)brow * N + bx * 128 + bcol;

    unsigned long long acc2[8][4];
#pragma unroll
    for (int i = 0; i < 8; i++)
#pragma unroll
        for (int j = 0; j < 4; j++) acc2[i][j] = 0ull;

    float4 av = *reinterpret_cast<const float4*>(Aptr);
    float4 bv = *reinterpret_cast<const float4*>(Bptr);

    const int KT = K >> 3;
    for (int kt = 0; kt < KT; kt++) {
        As[acol + 0][arow] = av.x;
        As[acol + 1][arow] = av.y;
        As[acol + 2][arow] = av.z;
        As[acol + 3][arow] = av.w;
        *reinterpret_cast<float4*>(&Bs[brow][bcol]) = bv;
        __syncthreads();
        if (kt + 1 < KT) {  // register prefetch of next K-slab
            av = *reinterpret_cast<const float4*>(Aptr + (kt + 1) * 8);
            bv = *reinterpret_cast<const float4*>(Bptr + (size_t)(kt + 1) * 8 * N);
        }
#pragma unroll
        for (int k = 0; k < 8; k++) {
            float4 a0 = *reinterpret_cast<const float4*>(&As[k][ty * 8]);
            float4 a1 = *reinterpret_cast<const float4*>(&As[k][ty * 8 + 4]);
            unsigned long long b2[4];
            const unsigned long long* bp =
                reinterpret_cast<const unsigned long long*>(&Bs[k][tx * 8]);
            b2[0] = bp[0]; b2[1] = bp[1]; b2[2] = bp[2]; b2[3] = bp[3];
            float a[8] = {a0.x, a0.y, a0.z, a0.w, a1.x, a1.y, a1.z, a1.w};
#pragma unroll
            for (int i = 0; i < 8; i++) {
                unsigned long long apk;
                asm("mov.b64 %0, {%1, %1};" : "=l"(apk) : "r"(__float_as_uint(a[i])));
#pragma unroll
                for (int j = 0; j < 4; j++) {
                    asm("fma.rn.f32x2 %0, %1, %2, %0;"
                        : "+l"(acc2[i][j]) : "l"(apk), "l"(b2[j]));
                }
            }
        }
        __syncthreads();
    }

    // Epilogue
    const int col0 = bx * 128 + tx * 8;
    float bb[8];
#pragma unroll
    for (int j = 0; j < 8; j++) bb[j] = bias[col0 + j];

#pragma unroll
    for (int i = 0; i < 8; i++) {
        const int row = by * 128 + ty * 8 + i;
        float out[8];
#pragma unroll
        for (int j2 = 0; j2 < 4; j2++) {
            unsigned long long u = acc2[i][j2];
            out[2 * j2]     = __uint_as_float((unsigned)(u & 0xffffffffull));
            out[2 * j2 + 1] = __uint_as_float((unsigned)(u >> 32));
        }
        float* cp = C + (size_t)row * N + col0;
        if (MODE == 0) {
            float4 r0, r1;
            r0.x = out[0] + bb[0]; r0.y = out[1] + bb[1];
            r0.z = out[2] + bb[2]; r0.w = out[3] + bb[3];
            r1.x = out[4] + bb[4]; r1.y = out[5] + bb[5];
            r1.z = out[6] + bb[6]; r1.w = out[7] + bb[7];
            reinterpret_cast<float4*>(cp)[0] = r0;
            reinterpret_cast<float4*>(cp)[1] = r1;
        } else {
            const float g = g_gate[(size_t)row * E_ + expert];
            float4 o0, o1;
            if (!isFirst) {
                o0 = reinterpret_cast<const float4*>(cp)[0];
                o1 = reinterpret_cast<const float4*>(cp)[1];
            } else {
                o0 = make_float4(0.f, 0.f, 0.f, 0.f);
                o1 = make_float4(0.f, 0.f, 0.f, 0.f);
            }
            o0.x += g * (out[0] + bb[0]); o0.y += g * (out[1] + bb[1]);
            o0.z += g * (out[2] + bb[2]); o0.w += g * (out[3] + bb[3]);
            o1.x += g * (out[4] + bb[4]); o1.y += g * (out[5] + bb[5]);
            o1.z += g * (out[6] + bb[6]); o1.w += g * (out[7] + bb[7]);
            reinterpret_cast<float4*>(cp)[0] = o0;
            reinterpret_cast<float4*>(cp)[1] = o1;
        }
    }
}

// ---------------------------------------------------------------------------
// mish + LayerNorm (affine-free), in place. One block per row of H_=2048.
// ---------------------------------------------------------------------------
__device__ __forceinline__ float block_reduce_sum(float v, float* sred) {
    __syncthreads();  // protect sred reuse across successive calls
#pragma unroll
    for (int o = 16; o > 0; o >>= 1) v += __shfl_xor_sync(0xffffffffu, v, o);
    const int w = threadIdx.x >> 5;
    if ((threadIdx.x & 31) == 0) sred[w] = v;
    __syncthreads();
    if (threadIdx.x < 32) {
        float r = (threadIdx.x < 8) ? sred[threadIdx.x] : 0.f;
#pragma unroll
        for (int o = 4; o > 0; o >>= 1) r += __shfl_xor_sync(0xffffffffu, r, o);
        if (threadIdx.x == 0) sred[0] = r;
    }
    __syncthreads();
    return sred[0];
}

__global__ void mish_ln_kernel(float* __restrict__ buf) {
    __shared__ float sred[32];
    const int t = threadIdx.x;
    float4* p = reinterpret_cast<float4*>(buf + (size_t)blockIdx.x * H_);
    float4 v0 = p[t], v1 = p[t + 256];
    float vals[8] = {v0.x, v0.y, v0.z, v0.w, v1.x, v1.y, v1.z, v1.w};
    float s = 0.f;
#pragma unroll
    for (int i = 0; i < 8; i++) {
        float h = vals[i];
        float sp = (h > 20.f) ? h : log1pf(expf(h));
        float m = h * tanhf(sp);
        vals[i] = m;
        s += m;
    }
    s = block_reduce_sum(s, sred);
    const float mu = s * (1.f / H_);
    float q = 0.f;
#pragma unroll
    for (int i = 0; i < 8; i++) {
        float d = vals[i] - mu;
        q += d * d;
    }
    q = block_reduce_sum(q, sred);
    const float inv = rsqrtf(q * (1.f / H_) + 1e-5f);
#pragma unroll
    for (int i = 0; i < 8; i++) vals[i] = (vals[i] - mu) * inv;
    v0 = make_float4(vals[0], vals[1], vals[2], vals[3]);
    v1 = make_float4(vals[4], vals[5], vals[6], vals[7]);
    p[t] = v0;
    p[t + 256] = v1;
}

// ---------------------------------------------------------------------------
// Launch
// ---------------------------------------------------------------------------
extern "C" void kernel_launch(void* const* d_in, const int* in_sizes, int n_in,
                              void* d_out, int out_size) {
    const float* x  = (const float*)d_in[0];
    const float* Wg = (const float*)d_in[1];
    const float* bg = (const float*)d_in[2];
    const float* W1 = (const float*)d_in[3];
    const float* b1 = (const float*)d_in[4];
    const float* W2 = (const float*)d_in[5];
    const float* b2 = (const float*)d_in[6];
    const float* W3 = (const float*)d_in[7];
    const float* b3 = (const float*)d_in[8];
    const float* W4 = (const float*)d_in[9];
    const float* b4 = (const float*)d_in[10];
    const float* W5 = (const float*)d_in[11];
    const float* b5 = (const float*)d_in[12];
    float* out = (float*)d_out;

    float *bufA, *bufB;
    cudaGetSymbolAddress((void**)&bufA, g_bufA);
    cudaGetSymbolAddress((void**)&bufB, g_bufB);

    gate_kernel<<<B_ / 8, 256>>>(x, Wg, bg);

    const dim3 gridH(H_ / 128, B_ / 128);      // N=2048 layers
    const dim3 gridO(DOUT_ / 128, B_ / 128);   // N=1024 final layer

    for (int e = 0; e < E_; e++) {
        const float* W1e = W1 + (size_t)e * DIN_ * H_;
        const float* W2e = W2 + (size_t)e * H_ * H_;
        const float* W3e = W3 + (size_t)e * H_ * H_;
        const float* W4e = W4 + (size_t)e * H_ * H_;
        const float* W5e = W5 + (size_t)e * H_ * DOUT_;
        const float* b1e = b1 + (size_t)e * H_;
        const float* b2e = b2 + (size_t)e * H_;
        const float* b3e = b3 + (size_t)e * H_;
        const float* b4e = b4 + (size_t)e * H_;
        const float* b5e = b5 + (size_t)e * DOUT_;

        gemm_kernel<0><<<gridH, 256>>>(x, W1e, b1e, bufA, B_, H_, DIN_, 0, 0);
        mish_ln_kernel<<<B_, 256>>>(bufA);
        gemm_kernel<0><<<gridH, 256>>>(bufA, W2e, b2e, bufB, B_, H_, H_, 0, 0);
        mish_ln_kernel<<<B_, 256>>>(bufB);
        gemm_kernel<0><<<gridH, 256>>>(bufB, W3e, b3e, bufA, B_, H_, H_, 0, 0);
        mish_ln_kernel<<<B_, 256>>>(bufA);
        gemm_kernel<0><<<gridH, 256>>>(bufA, W4e, b4e, bufB, B_, H_, H_, 0, 0);
        mish_ln_kernel<<<B_, 256>>>(bufB);
        gemm_kernel<1><<<gridO, 256>>>(bufB, W5e, b5e, out, B_, DOUT_, H_,
                                       e, (e == 0) ? 1 : 0);
    }
}

// round 3
// speedup vs baseline: 1.9882x; 1.9882x over previous
#include <cuda_runtime.h>
#include <cuda_bf16.h>
#include <math.h>
#include <stdint.h>

#define B_    8192
#define DIN_  1024
#define H_    2048
#define DOUT_ 1024
#define E_    8

// ---------------------------------------------------------------------------
// Scratch (allocation-free __device__ globals)
// ---------------------------------------------------------------------------
#define WPE 16777216ull  // weight elements per expert (all 5 layers, transposed)
__device__ unsigned short g_Whi[WPE * E_];
__device__ unsigned short g_Wlo[WPE * E_];
__device__ unsigned short g_xhi[(size_t)B_ * DIN_];
__device__ unsigned short g_xlo[(size_t)B_ * DIN_];
__device__ unsigned short g_Ahi[(size_t)B_ * H_];
__device__ unsigned short g_Alo[(size_t)B_ * H_];
__device__ float g_C[(size_t)B_ * H_];
__device__ float g_gate[(size_t)B_ * E_];

// ---------------------------------------------------------------------------
// PTX helpers
// ---------------------------------------------------------------------------
__device__ __forceinline__ uint32_t smem_to_u32(const void* smem_ptr) {
    uint32_t addr;
    asm("{ .reg .u64 tmp; cvta.to.shared.u64 tmp, %1; cvt.u32.u64 %0, tmp; }"
        : "=r"(addr) : "l"(smem_ptr));
    return addr;
}

#define CP_ASYNC16(dst, src) \
    asm volatile("cp.async.cg.shared.global [%0], [%1], 16;" \
                 :: "r"((uint32_t)(dst)), "l"(src) : "memory")

__device__ __forceinline__ void ldsm_x4(uint32_t* r, uint32_t addr) {
    asm volatile("ldmatrix.sync.aligned.m8n8.x4.shared.b16 {%0,%1,%2,%3}, [%4];"
                 : "=r"(r[0]), "=r"(r[1]), "=r"(r[2]), "=r"(r[3]) : "r"(addr));
}

__device__ __forceinline__ void mma_bf16(float* c, const uint32_t* a, const uint32_t* b) {
    asm volatile(
        "mma.sync.aligned.m16n8k16.row.col.f32.bf16.bf16.f32 "
        "{%0,%1,%2,%3}, {%4,%5,%6,%7}, {%8,%9}, {%0,%1,%2,%3};"
        : "+f"(c[0]), "+f"(c[1]), "+f"(c[2]), "+f"(c[3])
        : "r"(a[0]), "r"(a[1]), "r"(a[2]), "r"(a[3]), "r"(b[0]), "r"(b[1]));
}

// ---------------------------------------------------------------------------
// Gate: softmax(x @ Wg + bg) per row. One warp/row.
// ---------------------------------------------------------------------------
__global__ void gate_kernel(const float* __restrict__ x,
                            const float* __restrict__ Wg,
                            const float* __restrict__ bg) {
    int gwarp = (blockIdx.x * blockDim.x + threadIdx.x) >> 5;
    int lane  = threadIdx.x & 31;
    if (gwarp >= B_) return;
    const float* xr = x + (size_t)gwarp * DIN_;
    float acc[E_];
#pragma unroll
    for (int e = 0; e < E_; e++) acc[e] = 0.f;
    for (int i = lane; i < DIN_; i += 32) {
        float xv = xr[i];
        const float4* w4 = reinterpret_cast<const float4*>(Wg + (size_t)i * E_);
        float4 w0 = w4[0], w1 = w4[1];
        acc[0] += xv * w0.x; acc[1] += xv * w0.y;
        acc[2] += xv * w0.z; acc[3] += xv * w0.w;
        acc[4] += xv * w1.x; acc[5] += xv * w1.y;
        acc[6] += xv * w1.z; acc[7] += xv * w1.w;
    }
#pragma unroll
    for (int e = 0; e < E_; e++) {
#pragma unroll
        for (int o = 16; o > 0; o >>= 1)
            acc[e] += __shfl_xor_sync(0xffffffffu, acc[e], o);
    }
    if (lane == 0) {
        float mx = -1e30f;
#pragma unroll
        for (int e = 0; e < E_; e++) { acc[e] += bg[e]; mx = fmaxf(mx, acc[e]); }
        float s = 0.f;
#pragma unroll
        for (int e = 0; e < E_; e++) { acc[e] = expf(acc[e] - mx); s += acc[e]; }
        float inv = 1.f / s;
#pragma unroll
        for (int e = 0; e < E_; e++) g_gate[(size_t)gwarp * E_ + e] = acc[e] * inv;
    }
}

// ---------------------------------------------------------------------------
// Weight convert+transpose: W [K,N] fp32 -> Wt_hi/Wt_lo [N,K] bf16 split.
// ---------------------------------------------------------------------------
__global__ void wconv_kernel(const float* __restrict__ W,
                             __nv_bfloat16* __restrict__ Whi,
                             __nv_bfloat16* __restrict__ Wlo,
                             int K, int N) {
    __shared__ float t[32][33];
    const int n0 = blockIdx.x * 32, k0 = blockIdx.y * 32;
    const int tx = threadIdx.x, ty = threadIdx.y;  // 32x8
#pragma unroll
    for (int i = ty; i < 32; i += 8)
        t[i][tx] = W[(size_t)(k0 + i) * N + n0 + tx];
    __syncthreads();
#pragma unroll
    for (int i = ty; i < 32; i += 8) {
        float v = t[tx][i];  // = W[k0+tx][n0+i]
        __nv_bfloat16 h = __float2bfloat16(v);
        __nv_bfloat16 l = __float2bfloat16(v - __bfloat162float(h));
        size_t o = (size_t)(n0 + i) * K + k0 + tx;
        Whi[o] = h; Wlo[o] = l;
    }
}

// ---------------------------------------------------------------------------
// x convert: fp32 -> bf16 hi/lo.
// ---------------------------------------------------------------------------
__global__ void xconv_kernel(const float* __restrict__ x,
                             __nv_bfloat16* __restrict__ xhi,
                             __nv_bfloat16* __restrict__ xlo, int n4) {
    int i = blockIdx.x * blockDim.x + threadIdx.x;
    if (i >= n4) return;
    float4 v = reinterpret_cast<const float4*>(x)[i];
    float vv[4] = {v.x, v.y, v.z, v.w};
    unsigned short h[4], l[4];
#pragma unroll
    for (int j = 0; j < 4; j++) {
        __nv_bfloat16 hb = __float2bfloat16(vv[j]);
        __nv_bfloat16 lb = __float2bfloat16(vv[j] - __bfloat162float(hb));
        h[j] = __bfloat16_as_ushort(hb);
        l[j] = __bfloat16_as_ushort(lb);
    }
    reinterpret_cast<ushort4*>(xhi)[i] = make_ushort4(h[0], h[1], h[2], h[3]);
    reinterpret_cast<ushort4*>(xlo)[i] = make_ushort4(l[0], l[1], l[2], l[3]);
}

// ---------------------------------------------------------------------------
// mish + LayerNorm + bf16 hi/lo convert. Row of H_=2048, 256 threads.
// ---------------------------------------------------------------------------
__device__ __forceinline__ float block_reduce_sum(float v, float* sred) {
    __syncthreads();
#pragma unroll
    for (int o = 16; o > 0; o >>= 1) v += __shfl_xor_sync(0xffffffffu, v, o);
    const int w = threadIdx.x >> 5;
    if ((threadIdx.x & 31) == 0) sred[w] = v;
    __syncthreads();
    if (threadIdx.x < 32) {
        float r = (threadIdx.x < 8) ? sred[threadIdx.x] : 0.f;
#pragma unroll
        for (int o = 4; o > 0; o >>= 1) r += __shfl_xor_sync(0xffffffffu, r, o);
        if (threadIdx.x == 0) sred[0] = r;
    }
    __syncthreads();
    return sred[0];
}

__global__ void mish_ln_cvt_kernel(const float* __restrict__ in,
                                   __nv_bfloat16* __restrict__ ohi,
                                   __nv_bfloat16* __restrict__ olo) {
    __shared__ float sred[32];
    const int t = threadIdx.x;
    const size_t rowoff = (size_t)blockIdx.x * H_;
    const float4* p = reinterpret_cast<const float4*>(in + rowoff);
    float4 v0 = p[t], v1 = p[t + 256];
    float vals[8] = {v0.x, v0.y, v0.z, v0.w, v1.x, v1.y, v1.z, v1.w};
    float s = 0.f;
#pragma unroll
    for (int i = 0; i < 8; i++) {
        float h = vals[i];
        float sp = (h > 20.f) ? h : log1pf(expf(h));
        float m = h * tanhf(sp);
        vals[i] = m;
        s += m;
    }
    s = block_reduce_sum(s, sred);
    const float mu = s * (1.f / H_);
    float q = 0.f;
#pragma unroll
    for (int i = 0; i < 8; i++) { float d = vals[i] - mu; q += d * d; }
    q = block_reduce_sum(q, sred);
    const float inv = rsqrtf(q * (1.f / H_) + 1e-5f);
    unsigned short h8[8], l8[8];
#pragma unroll
    for (int i = 0; i < 8; i++) {
        float v = (vals[i] - mu) * inv;
        __nv_bfloat16 hb = __float2bfloat16(v);
        __nv_bfloat16 lb = __float2bfloat16(v - __bfloat162float(hb));
        h8[i] = __bfloat16_as_ushort(hb);
        l8[i] = __bfloat16_as_ushort(lb);
    }
    ushort4* oh = reinterpret_cast<ushort4*>(ohi + rowoff);
    ushort4* ol = reinterpret_cast<ushort4*>(olo + rowoff);
    oh[t]       = make_ushort4(h8[0], h8[1], h8[2], h8[3]);
    oh[t + 256] = make_ushort4(h8[4], h8[5], h8[6], h8[7]);
    ol[t]       = make_ushort4(l8[0], l8[1], l8[2], l8[3]);
    ol[t + 256] = make_ushort4(l8[4], l8[5], l8[6], l8[7]);
}

// ---------------------------------------------------------------------------
// HMMA split-bf16 GEMM. CTA 128x128, warp 64x32, K-chunk 32, 4-stage cp.async.
// A: [M,K] bf16 hi/lo K-major. B: [N,K] bf16 hi/lo K-major (transposed W).
// D = Ah@Bh^T + Ah@Bl^T + Al@Bh^T (fp32 accum).
// MODE 0: C = D + bias[col]
// MODE 1: C (+)= gate[row,expert] * (D + bias[col])   (isFirst -> '=')
// ---------------------------------------------------------------------------
#define STRIDE_E 40                      // padded row stride in bf16 elems (80B)
#define MAT_BYTES (128 * STRIDE_E * 2)   // 10240
#define STAGE_BYTES (4 * MAT_BYTES)      // 40960
#define NSTAGE 4
#define GEMM_SMEM (NSTAGE * STAGE_BYTES) // 163840

__device__ __forceinline__ void copy_stage(uint32_t st, int tid, int kc, int K,
                                           const __nv_bfloat16* aH, const __nv_bfloat16* aL,
                                           const __nv_bfloat16* bH, const __nv_bfloat16* bL) {
    const __nv_bfloat16* srcs[4] = {aH, aL, bH, bL};
#pragma unroll
    for (int m = 0; m < 4; m++) {
#pragma unroll
        for (int q = 0; q < 2; q++) {
            int c = tid * 2 + q;          // 0..511
            int row = c >> 2;             // 0..127
            int kch = c & 3;              // 0..3 (16B chunks of the 64B row)
            uint32_t dst = st + m * MAT_BYTES + row * (STRIDE_E * 2) + kch * 16;
            const __nv_bfloat16* src = srcs[m] + (size_t)row * K + kc * 32 + kch * 8;
            CP_ASYNC16(dst, src);
        }
    }
    asm volatile("cp.async.commit_group;" ::: "memory");
}

template <int MODE>
__global__ __launch_bounds__(256, 1)
void tc_gemm(const __nv_bfloat16* __restrict__ Ahi, const __nv_bfloat16* __restrict__ Alo,
             const __nv_bfloat16* __restrict__ Bhi, const __nv_bfloat16* __restrict__ Blo,
             const float* __restrict__ bias, float* __restrict__ C,
             int N, int K, int expert, int isFirst) {
    extern __shared__ __align__(16) char dynsmem[];
    const uint32_t sbase = smem_to_u32(dynsmem);

    const int tid = threadIdx.x;
    const int wid = tid >> 5;
    const int lane = tid & 31;
    const int wm = wid & 1;       // 2 warps in M
    const int wn = wid >> 1;      // 4 warps in N
    const int KT = K >> 5;

    const __nv_bfloat16* aH = Ahi + (size_t)(blockIdx.y * 128) * K;
    const __nv_bfloat16* aL = Alo + (size_t)(blockIdx.y * 128) * K;
    const __nv_bfloat16* bH = Bhi + (size_t)(blockIdx.x * 128) * K;
    const __nv_bfloat16* bL = Blo + (size_t)(blockIdx.x * 128) * K;

    float acc[4][4][4];
#pragma unroll
    for (int i = 0; i < 4; i++)
#pragma unroll
        for (int j = 0; j < 4; j++)
#pragma unroll
            for (int q = 0; q < 4; q++) acc[i][j][q] = 0.f;

    // Prologue: stages 0,1,2
    copy_stage(sbase + 0 * STAGE_BYTES, tid, 0, K, aH, aL, bH, bL);
    copy_stage(sbase + 1 * STAGE_BYTES, tid, 1, K, aH, aL, bH, bL);
    copy_stage(sbase + 2 * STAGE_BYTES, tid, 2, K, aH, aL, bH, bL);

    // Per-lane ldmatrix address components (byte offsets within a matrix tile)
    const uint32_t a_row = wm * 64 + (lane & 15);         // + i*16
    const uint32_t a_koff = (lane >> 4) * 16;             // k half (bytes)
    const uint32_t b_row = wn * 32 + (lane >> 4) * 8 + (lane & 7);  // + p*16
    const uint32_t b_koff = ((lane >> 3) & 1) * 16;

    for (int kc = 0; kc < KT; kc++) {
        if (kc + 3 < KT)      asm volatile("cp.async.wait_group 2;" ::: "memory");
        else if (kc + 2 < KT) asm volatile("cp.async.wait_group 1;" ::: "memory");
        else                  asm volatile("cp.async.wait_group 0;" ::: "memory");
        __syncthreads();

        const uint32_t st = sbase + (kc & 3) * STAGE_BYTES;
        const uint32_t Ah_b = st;
        const uint32_t Al_b = st + MAT_BYTES;
        const uint32_t Bh_b = st + 2 * MAT_BYTES;
        const uint32_t Bl_b = st + 3 * MAT_BYTES;

#pragma unroll
        for (int k16 = 0; k16 < 2; k16++) {
            const uint32_t kbyte = k16 * 32;
            uint32_t ah[16], al[16], bh[8], bl[8];
#pragma unroll
            for (int i = 0; i < 4; i++) {
                uint32_t off = (a_row + i * 16) * (STRIDE_E * 2) + kbyte + a_koff;
                ldsm_x4(&ah[i * 4], Ah_b + off);
                ldsm_x4(&al[i * 4], Al_b + off);
            }
#pragma unroll
            for (int p = 0; p < 2; p++) {
                uint32_t off = (b_row + p * 16) * (STRIDE_E * 2) + kbyte + b_koff;
                ldsm_x4(&bh[p * 4], Bh_b + off);
                ldsm_x4(&bl[p * 4], Bl_b + off);
            }
#pragma unroll
            for (int i = 0; i < 4; i++)
#pragma unroll
                for (int j = 0; j < 4; j++) {
                    const uint32_t* bhj = &bh[(j >> 1) * 4 + (j & 1) * 2];
                    const uint32_t* blj = &bl[(j >> 1) * 4 + (j & 1) * 2];
                    mma_bf16(acc[i][j], &ah[i * 4], bhj);
                    mma_bf16(acc[i][j], &ah[i * 4], blj);
                    mma_bf16(acc[i][j], &al[i * 4], bhj);
                }
        }
        __syncthreads();
        if (kc + 3 < KT)
            copy_stage(sbase + ((kc + 3) & 3) * STAGE_BYTES, tid, kc + 3, K, aH, aL, bH, bL);
    }

    // Epilogue
    const int r0 = blockIdx.y * 128 + wm * 64 + (lane >> 2);
    const int cbase = blockIdx.x * 128 + wn * 32 + (lane & 3) * 2;
#pragma unroll
    for (int i = 0; i < 4; i++) {
        const int rowA = r0 + i * 16;
        const int rowB = rowA + 8;
        float gA = 0.f, gB = 0.f;
        if (MODE == 1) {
            gA = g_gate[(size_t)rowA * E_ + expert];
            gB = g_gate[(size_t)rowB * E_ + expert];
        }
#pragma unroll
        for (int j = 0; j < 4; j++) {
            const int col = cbase + j * 8;
            float b0 = bias[col], b1 = bias[col + 1];
            float* pA = C + (size_t)rowA * N + col;
            float* pB = C + (size_t)rowB * N + col;
            if (MODE == 0) {
                float2 vA = make_float2(acc[i][j][0] + b0, acc[i][j][1] + b1);
                float2 vB = make_float2(acc[i][j][2] + b0, acc[i][j][3] + b1);
                *reinterpret_cast<float2*>(pA) = vA;
                *reinterpret_cast<float2*>(pB) = vB;
            } else {
                float2 oA = isFirst ? make_float2(0.f, 0.f)
                                    : *reinterpret_cast<const float2*>(pA);
                float2 oB = isFirst ? make_float2(0.f, 0.f)
                                    : *reinterpret_cast<const float2*>(pB);
                oA.x += gA * (acc[i][j][0] + b0);
                oA.y += gA * (acc[i][j][1] + b1);
                oB.x += gB * (acc[i][j][2] + b0);
                oB.y += gB * (acc[i][j][3] + b1);
                *reinterpret_cast<float2*>(pA) = oA;
                *reinterpret_cast<float2*>(pB) = oB;
            }
        }
    }
}

// ---------------------------------------------------------------------------
// Launch
// ---------------------------------------------------------------------------
extern "C" void kernel_launch(void* const* d_in, const int* in_sizes, int n_in,
                              void* d_out, int out_size) {
    const float* x  = (const float*)d_in[0];
    const float* Wg = (const float*)d_in[1];
    const float* bg = (const float*)d_in[2];
    const float* W1 = (const float*)d_in[3];
    const float* b1 = (const float*)d_in[4];
    const float* W2 = (const float*)d_in[5];
    const float* b2 = (const float*)d_in[6];
    const float* W3 = (const float*)d_in[7];
    const float* b3 = (const float*)d_in[8];
    const float* W4 = (const float*)d_in[9];
    const float* b4 = (const float*)d_in[10];
    const float* W5 = (const float*)d_in[11];
    const float* b5 = (const float*)d_in[12];
    float* out = (float*)d_out;

    void *pWhi, *pWlo, *pxhi, *pxlo, *pAhi, *pAlo, *pC;
    cudaGetSymbolAddress(&pWhi, g_Whi);
    cudaGetSymbolAddress(&pWlo, g_Wlo);
    cudaGetSymbolAddress(&pxhi, g_xhi);
    cudaGetSymbolAddress(&pxlo, g_xlo);
    cudaGetSymbolAddress(&pAhi, g_Ahi);
    cudaGetSymbolAddress(&pAlo, g_Alo);
    cudaGetSymbolAddress(&pC, g_C);
    __nv_bfloat16* Whi = (__nv_bfloat16*)pWhi;
    __nv_bfloat16* Wlo = (__nv_bfloat16*)pWlo;
    __nv_bfloat16* xhi = (__nv_bfloat16*)pxhi;
    __nv_bfloat16* xlo = (__nv_bfloat16*)pxlo;
    __nv_bfloat16* Ahi = (__nv_bfloat16*)pAhi;
    __nv_bfloat16* Alo = (__nv_bfloat16*)pAlo;
    float* Cbuf = (float*)pC;

    cudaFuncSetAttribute(tc_gemm<0>, cudaFuncAttributeMaxDynamicSharedMemorySize, GEMM_SMEM);
    cudaFuncSetAttribute(tc_gemm<1>, cudaFuncAttributeMaxDynamicSharedMemorySize, GEMM_SMEM);

    gate_kernel<<<B_ / 8, 256>>>(x, Wg, bg);
    xconv_kernel<<<(B_ * DIN_ / 4 + 255) / 256, 256>>>(x, xhi, xlo, B_ * DIN_ / 4);

    // Per-expert weight offsets within the packed transposed arrays
    const size_t off1 = 0;
    const size_t off2 = off1 + (size_t)DIN_ * H_;
    const size_t off3 = off2 + (size_t)H_ * H_;
    const size_t off4 = off3 + (size_t)H_ * H_;
    const size_t off5 = off4 + (size_t)H_ * H_;

    const dim3 wblk(32, 8);
    for (int e = 0; e < E_; e++) {
        const size_t eb = (size_t)e * WPE;
        wconv_kernel<<<dim3(H_ / 32, DIN_ / 32), wblk>>>(
            W1 + (size_t)e * DIN_ * H_, Whi + eb + off1, Wlo + eb + off1, DIN_, H_);
        wconv_kernel<<<dim3(H_ / 32, H_ / 32), wblk>>>(
            W2 + (size_t)e * H_ * H_, Whi + eb + off2, Wlo + eb + off2, H_, H_);
        wconv_kernel<<<dim3(H_ / 32, H_ / 32), wblk>>>(
            W3 + (size_t)e * H_ * H_, Whi + eb + off3, Wlo + eb + off3, H_, H_);
        wconv_kernel<<<dim3(H_ / 32, H_ / 32), wblk>>>(
            W4 + (size_t)e * H_ * H_, Whi + eb + off4, Wlo + eb + off4, H_, H_);
        wconv_kernel<<<dim3(DOUT_ / 32, H_ / 32), wblk>>>(
            W5 + (size_t)e * H_ * DOUT_, Whi + eb + off5, Wlo + eb + off5, H_, DOUT_);
    }

    const dim3 gridH(H_ / 128, B_ / 128);
    const dim3 gridO(DOUT_ / 128, B_ / 128);

    for (int e = 0; e < E_; e++) {
        const size_t eb = (size_t)e * WPE;
        const float* b1e = b1 + (size_t)e * H_;
        const float* b2e = b2 + (size_t)e * H_;
        const float* b3e = b3 + (size_t)e * H_;
        const float* b4e = b4 + (size_t)e * H_;
        const float* b5e = b5 + (size_t)e * DOUT_;

        tc_gemm<0><<<gridH, 256, GEMM_SMEM>>>(xhi, xlo, Whi + eb + off1, Wlo + eb + off1,
                                              b1e, Cbuf, H_, DIN_, 0, 0);
        mish_ln_cvt_kernel<<<B_, 256>>>(Cbuf, Ahi, Alo);
        tc_gemm<0><<<gridH, 256, GEMM_SMEM>>>(Ahi, Alo, Whi + eb + off2, Wlo + eb + off2,
                                              b2e, Cbuf, H_, H_, 0, 0);
        mish_ln_cvt_kernel<<<B_, 256>>>(Cbuf, Ahi, Alo);
        tc_gemm<0><<<gridH, 256, GEMM_SMEM>>>(Ahi, Alo, Whi + eb + off3, Wlo + eb + off3,
                                              b3e, Cbuf, H_, H_, 0, 0);
        mish_ln_cvt_kernel<<<B_, 256>>>(Cbuf, Ahi, Alo);
        tc_gemm<0><<<gridH, 256, GEMM_SMEM>>>(Ahi, Alo, Whi + eb + off4, Wlo + eb + off4,
                                              b4e, Cbuf, H_, H_, 0, 0);
        mish_ln_cvt_kernel<<<B_, 256>>>(Cbuf, Ahi, Alo);
        tc_gemm<1><<<gridO, 256, GEMM_SMEM>>>(Ahi, Alo, Whi + eb + off5, Wlo + eb + off5,
                                              b5e, out, DOUT_, H_, e, (e == 0) ? 1 : 0);
    }
}

// round 4
// speedup vs baseline: 2.0255x; 1.0188x over previous
#include <cuda_runtime.h>
#include <cuda_bf16.h>
#include <math.h>
#include <stdint.h>

#define B_    8192
#define DIN_  1024
#define H_    2048
#define DOUT_ 1024
#define E_    8

// ---------------------------------------------------------------------------
// Scratch (allocation-free __device__ globals)
// ---------------------------------------------------------------------------
#define WPE 16777216ull  // weight elements per expert (all 5 layers, transposed)
__device__ unsigned short g_Whi[WPE * E_];
__device__ unsigned short g_Wlo[WPE * E_];
__device__ unsigned short g_xhi[(size_t)B_ * DIN_];
__device__ unsigned short g_xlo[(size_t)B_ * DIN_];
__device__ unsigned short g_Ahi[(size_t)B_ * H_];
__device__ unsigned short g_Alo[(size_t)B_ * H_];
__device__ float g_C[(size_t)B_ * H_];
__device__ float g_gate[(size_t)B_ * E_];

// ---------------------------------------------------------------------------
// PTX helpers
// ---------------------------------------------------------------------------
__device__ __forceinline__ uint32_t smem_to_u32(const void* smem_ptr) {
    uint32_t addr;
    asm("{ .reg .u64 tmp; cvta.to.shared.u64 tmp, %1; cvt.u32.u64 %0, tmp; }"
        : "=r"(addr) : "l"(smem_ptr));
    return addr;
}

#define CP_ASYNC16(dst, src) \
    asm volatile("cp.async.cg.shared.global [%0], [%1], 16;" \
                 :: "r"((uint32_t)(dst)), "l"(src) : "memory")

__device__ __forceinline__ void ldsm_x4(uint32_t* r, uint32_t addr) {
    asm volatile("ldmatrix.sync.aligned.m8n8.x4.shared.b16 {%0,%1,%2,%3}, [%4];"
                 : "=r"(r[0]), "=r"(r[1]), "=r"(r[2]), "=r"(r[3]) : "r"(addr));
}

__device__ __forceinline__ void mma_bf16(float* c, const uint32_t* a, const uint32_t* b) {
    asm volatile(
        "mma.sync.aligned.m16n8k16.row.col.f32.bf16.bf16.f32 "
        "{%0,%1,%2,%3}, {%4,%5,%6,%7}, {%8,%9}, {%0,%1,%2,%3};"
        : "+f"(c[0]), "+f"(c[1]), "+f"(c[2]), "+f"(c[3])
        : "r"(a[0]), "r"(a[1]), "r"(a[2]), "r"(a[3]), "r"(b[0]), "r"(b[1]));
}

// ---------------------------------------------------------------------------
// Gate: softmax(x @ Wg + bg) per row. One warp/row.
// ---------------------------------------------------------------------------
__global__ void gate_kernel(const float* __restrict__ x,
                            const float* __restrict__ Wg,
                            const float* __restrict__ bg) {
    int gwarp = (blockIdx.x * blockDim.x + threadIdx.x) >> 5;
    int lane  = threadIdx.x & 31;
    if (gwarp >= B_) return;
    const float* xr = x + (size_t)gwarp * DIN_;
    float acc[E_];
#pragma unroll
    for (int e = 0; e < E_; e++) acc[e] = 0.f;
    for (int i = lane; i < DIN_; i += 32) {
        float xv = xr[i];
        const float4* w4 = reinterpret_cast<const float4*>(Wg + (size_t)i * E_);
        float4 w0 = w4[0], w1 = w4[1];
        acc[0] += xv * w0.x; acc[1] += xv * w0.y;
        acc[2] += xv * w0.z; acc[3] += xv * w0.w;
        acc[4] += xv * w1.x; acc[5] += xv * w1.y;
        acc[6] += xv * w1.z; acc[7] += xv * w1.w;
    }
#pragma unroll
    for (int e = 0; e < E_; e++) {
#pragma unroll
        for (int o = 16; o > 0; o >>= 1)
            acc[e] += __shfl_xor_sync(0xffffffffu, acc[e], o);
    }
    if (lane == 0) {
        float mx = -1e30f;
#pragma unroll
        for (int e = 0; e < E_; e++) { acc[e] += bg[e]; mx = fmaxf(mx, acc[e]); }
        float s = 0.f;
#pragma unroll
        for (int e = 0; e < E_; e++) { acc[e] = expf(acc[e] - mx); s += acc[e]; }
        float inv = 1.f / s;
#pragma unroll
        for (int e = 0; e < E_; e++) g_gate[(size_t)gwarp * E_ + e] = acc[e] * inv;
    }
}

// ---------------------------------------------------------------------------
// Weight convert+transpose: W [K,N] fp32 -> Wt_hi/Wt_lo [N,K] bf16 split.
// Tile 64(k) x 32(n); ushort2 stores -> 4B-coalesced writes.
// ---------------------------------------------------------------------------
__global__ void wconv_kernel(const float* __restrict__ W,
                             __nv_bfloat16* __restrict__ Whi,
                             __nv_bfloat16* __restrict__ Wlo,
                             int K, int N) {
    __shared__ float t[64][33];
    const int n0 = blockIdx.x * 32, k0 = blockIdx.y * 64;
    const int tx = threadIdx.x, ty = threadIdx.y;  // 32x8
#pragma unroll
    for (int r = 0; r < 8; r++) {
        int k = ty + r * 8;
        t[k][tx] = W[(size_t)(k0 + k) * N + n0 + tx];
    }
    __syncthreads();
#pragma unroll
    for (int r = 0; r < 4; r++) {
        int n = ty + r * 8;
        float v0 = t[2 * tx][n];
        float v1 = t[2 * tx + 1][n];
        __nv_bfloat16 h0 = __float2bfloat16(v0);
        __nv_bfloat16 l0 = __float2bfloat16(v0 - __bfloat162float(h0));
        __nv_bfloat16 h1 = __float2bfloat16(v1);
        __nv_bfloat16 l1 = __float2bfloat16(v1 - __bfloat162float(h1));
        size_t o = (size_t)(n0 + n) * K + k0 + 2 * tx;
        *reinterpret_cast<ushort2*>(&Whi[o]) =
            make_ushort2(__bfloat16_as_ushort(h0), __bfloat16_as_ushort(h1));
        *reinterpret_cast<ushort2*>(&Wlo[o]) =
            make_ushort2(__bfloat16_as_ushort(l0), __bfloat16_as_ushort(l1));
    }
}

// ---------------------------------------------------------------------------
// x convert: fp32 -> bf16 hi/lo.
// ---------------------------------------------------------------------------
__global__ void xconv_kernel(const float* __restrict__ x,
                             __nv_bfloat16* __restrict__ xhi,
                             __nv_bfloat16* __restrict__ xlo, int n4) {
    int i = blockIdx.x * blockDim.x + threadIdx.x;
    if (i >= n4) return;
    float4 v = reinterpret_cast<const float4*>(x)[i];
    float vv[4] = {v.x, v.y, v.z, v.w};
    unsigned short h[4], l[4];
#pragma unroll
    for (int j = 0; j < 4; j++) {
        __nv_bfloat16 hb = __float2bfloat16(vv[j]);
        __nv_bfloat16 lb = __float2bfloat16(vv[j] - __bfloat162float(hb));
        h[j] = __bfloat16_as_ushort(hb);
        l[j] = __bfloat16_as_ushort(lb);
    }
    reinterpret_cast<ushort4*>(xhi)[i] = make_ushort4(h[0], h[1], h[2], h[3]);
    reinterpret_cast<ushort4*>(xlo)[i] = make_ushort4(l[0], l[1], l[2], l[3]);
}

// ---------------------------------------------------------------------------
// mish + LayerNorm + bf16 hi/lo convert. Row of H_=2048, 256 threads.
// ---------------------------------------------------------------------------
__device__ __forceinline__ float block_reduce_sum(float v, float* sred) {
    __syncthreads();
#pragma unroll
    for (int o = 16; o > 0; o >>= 1) v += __shfl_xor_sync(0xffffffffu, v, o);
    const int w = threadIdx.x >> 5;
    if ((threadIdx.x & 31) == 0) sred[w] = v;
    __syncthreads();
    if (threadIdx.x < 32) {
        float r = (threadIdx.x < 8) ? sred[threadIdx.x] : 0.f;
#pragma unroll
        for (int o = 4; o > 0; o >>= 1) r += __shfl_xor_sync(0xffffffffu, r, o);
        if (threadIdx.x == 0) sred[0] = r;
    }
    __syncthreads();
    return sred[0];
}

__global__ void mish_ln_cvt_kernel(const float* __restrict__ in,
                                   __nv_bfloat16* __restrict__ ohi,
                                   __nv_bfloat16* __restrict__ olo) {
    __shared__ float sred[32];
    const int t = threadIdx.x;
    const size_t rowoff = (size_t)blockIdx.x * H_;
    const float4* p = reinterpret_cast<const float4*>(in + rowoff);
    float4 v0 = p[t], v1 = p[t + 256];
    float vals[8] = {v0.x, v0.y, v0.z, v0.w, v1.x, v1.y, v1.z, v1.w};
    float s = 0.f;
#pragma unroll
    for (int i = 0; i < 8; i++) {
        float h = vals[i];
        float sp = (h > 20.f) ? h : log1pf(expf(h));
        float m = h * tanhf(sp);
        vals[i] = m;
        s += m;
    }
    s = block_reduce_sum(s, sred);
    const float mu = s * (1.f / H_);
    float q = 0.f;
#pragma unroll
    for (int i = 0; i < 8; i++) { float d = vals[i] - mu; q += d * d; }
    q = block_reduce_sum(q, sred);
    const float inv = rsqrtf(q * (1.f / H_) + 1e-5f);
    unsigned short h8[8], l8[8];
#pragma unroll
    for (int i = 0; i < 8; i++) {
        float v = (vals[i] - mu) * inv;
        __nv_bfloat16 hb = __float2bfloat16(v);
        __nv_bfloat16 lb = __float2bfloat16(v - __bfloat162float(hb));
        h8[i] = __bfloat16_as_ushort(hb);
        l8[i] = __bfloat16_as_ushort(lb);
    }
    ushort4* oh = reinterpret_cast<ushort4*>(ohi + rowoff);
    ushort4* ol = reinterpret_cast<ushort4*>(olo + rowoff);
    oh[t]       = make_ushort4(h8[0], h8[1], h8[2], h8[3]);
    oh[t + 256] = make_ushort4(h8[4], h8[5], h8[6], h8[7]);
    ol[t]       = make_ushort4(l8[0], l8[1], l8[2], l8[3]);
    ol[t + 256] = make_ushort4(l8[4], l8[5], l8[6], l8[7]);
}

// ---------------------------------------------------------------------------
// HMMA split-bf16 GEMM. CTA 128x128, warp 64x32, K-chunk 32, 4-stage cp.async.
// One __syncthreads per chunk; full-chunk frag load; MMAs grouped by pass
// (hh, hl, lh) x 16 independent (i,j) tiles to kill acc RAW chains.
// ---------------------------------------------------------------------------
#define STRIDE_E 40                      // padded row stride in bf16 elems (80B)
#define MAT_BYTES (128 * STRIDE_E * 2)   // 10240
#define STAGE_BYTES (4 * MAT_BYTES)      // 40960
#define NSTAGE 4
#define GEMM_SMEM (NSTAGE * STAGE_BYTES) // 163840

__device__ __forceinline__ void copy_stage(uint32_t st, int tid, int kc, int K,
                                           const __nv_bfloat16* aH, const __nv_bfloat16* aL,
                                           const __nv_bfloat16* bH, const __nv_bfloat16* bL) {
    const __nv_bfloat16* srcs[4] = {aH, aL, bH, bL};
#pragma unroll
    for (int m = 0; m < 4; m++) {
#pragma unroll
        for (int q = 0; q < 2; q++) {
            int c = tid * 2 + q;          // 0..511
            int row = c >> 2;             // 0..127
            int kch = c & 3;              // 0..3 (16B chunks of the 64B row)
            uint32_t dst = st + m * MAT_BYTES + row * (STRIDE_E * 2) + kch * 16;
            const __nv_bfloat16* src = srcs[m] + (size_t)row * K + kc * 32 + kch * 8;
            CP_ASYNC16(dst, src);
        }
    }
    asm volatile("cp.async.commit_group;" ::: "memory");
}

template <int MODE>
__global__ __launch_bounds__(256, 1)
void tc_gemm(const __nv_bfloat16* __restrict__ Ahi, const __nv_bfloat16* __restrict__ Alo,
             const __nv_bfloat16* __restrict__ Bhi, const __nv_bfloat16* __restrict__ Blo,
             const float* __restrict__ bias, float* __restrict__ C,
             int N, int K, int expert, int isFirst) {
    extern __shared__ __align__(16) char dynsmem[];
    const uint32_t sbase = smem_to_u32(dynsmem);

    const int tid = threadIdx.x;
    const int wid = tid >> 5;
    const int lane = tid & 31;
    const int wm = wid & 1;       // 2 warps in M
    const int wn = wid >> 1;      // 4 warps in N
    const int KT = K >> 5;

    const __nv_bfloat16* aH = Ahi + (size_t)(blockIdx.y * 128) * K;
    const __nv_bfloat16* aL = Alo + (size_t)(blockIdx.y * 128) * K;
    const __nv_bfloat16* bH = Bhi + (size_t)(blockIdx.x * 128) * K;
    const __nv_bfloat16* bL = Blo + (size_t)(blockIdx.x * 128) * K;

    float acc[4][4][4];
#pragma unroll
    for (int i = 0; i < 4; i++)
#pragma unroll
        for (int j = 0; j < 4; j++)
#pragma unroll
            for (int q = 0; q < 4; q++) acc[i][j][q] = 0.f;

    // Prologue: stages 0,1,2
    copy_stage(sbase + 0 * STAGE_BYTES, tid, 0, K, aH, aL, bH, bL);
    copy_stage(sbase + 1 * STAGE_BYTES, tid, 1, K, aH, aL, bH, bL);
    copy_stage(sbase + 2 * STAGE_BYTES, tid, 2, K, aH, aL, bH, bL);

    // Per-lane ldmatrix address components (byte offsets within a matrix tile)
    const uint32_t a_row = wm * 64 + (lane & 15);         // + i*16
    const uint32_t a_koff = (lane >> 4) * 16;             // k half (bytes)
    const uint32_t b_row = wn * 32 + (lane >> 4) * 8 + (lane & 7);  // + p*16
    const uint32_t b_koff = ((lane >> 3) & 1) * 16;

    for (int kc = 0; kc < KT; kc++) {
        if (kc + 2 < KT)      asm volatile("cp.async.wait_group 2;" ::: "memory");
        else if (kc + 1 < KT) asm volatile("cp.async.wait_group 1;" ::: "memory");
        else                  asm volatile("cp.async.wait_group 0;" ::: "memory");
        __syncthreads();
        // Stage (kc-1)&3 was fully consumed before the barrier above -> refill it.
        if (kc + 3 < KT)
            copy_stage(sbase + ((kc + 3) & 3) * STAGE_BYTES, tid, kc + 3, K, aH, aL, bH, bL);

        const uint32_t st = sbase + (kc & 3) * STAGE_BYTES;
        const uint32_t Ah_b = st;
        const uint32_t Al_b = st + MAT_BYTES;
        const uint32_t Bh_b = st + 2 * MAT_BYTES;
        const uint32_t Bl_b = st + 3 * MAT_BYTES;

        // Load BOTH k16 halves' fragments up front (24 independent ldsm.x4)
        uint32_t ah[2][16], al[2][16], bh[2][8], bl[2][8];
#pragma unroll
        for (int h = 0; h < 2; h++) {
            const uint32_t kbyte = h * 32;
#pragma unroll
            for (int i = 0; i < 4; i++) {
                uint32_t off = (a_row + i * 16) * (STRIDE_E * 2) + kbyte + a_koff;
                ldsm_x4(&ah[h][i * 4], Ah_b + off);
                ldsm_x4(&al[h][i * 4], Al_b + off);
            }
#pragma unroll
            for (int p = 0; p < 2; p++) {
                uint32_t off = (b_row + p * 16) * (STRIDE_E * 2) + kbyte + b_koff;
                ldsm_x4(&bh[h][p * 4], Bh_b + off);
                ldsm_x4(&bl[h][p * 4], Bl_b + off);
            }
        }
        // 96 MMAs grouped by pass: 16 independent acc tiles between any reuse
#pragma unroll
        for (int h = 0; h < 2; h++) {
#pragma unroll
            for (int i = 0; i < 4; i++)
#pragma unroll
                for (int j = 0; j < 4; j++)
                    mma_bf16(acc[i][j], &ah[h][i * 4], &bh[h][(j >> 1) * 4 + (j & 1) * 2]);
#pragma unroll
            for (int i = 0; i < 4; i++)
#pragma unroll
                for (int j = 0; j < 4; j++)
                    mma_bf16(acc[i][j], &ah[h][i * 4], &bl[h][(j >> 1) * 4 + (j & 1) * 2]);
#pragma unroll
            for (int i = 0; i < 4; i++)
#pragma unroll
                for (int j = 0; j < 4; j++)
                    mma_bf16(acc[i][j], &al[h][i * 4], &bh[h][(j >> 1) * 4 + (j & 1) * 2]);
        }
    }

    // Epilogue
    const int r0 = blockIdx.y * 128 + wm * 64 + (lane >> 2);
    const int cbase = blockIdx.x * 128 + wn * 32 + (lane & 3) * 2;
#pragma unroll
    for (int i = 0; i < 4; i++) {
        const int rowA = r0 + i * 16;
        const int rowB = rowA + 8;
        float gA = 0.f, gB = 0.f;
        if (MODE == 1) {
            gA = g_gate[(size_t)rowA * E_ + expert];
            gB = g_gate[(size_t)rowB * E_ + expert];
        }
#pragma unroll
        for (int j = 0; j < 4; j++) {
            const int col = cbase + j * 8;
            float b0 = bias[col], b1 = bias[col + 1];
            float* pA = C + (size_t)rowA * N + col;
            float* pB = C + (size_t)rowB * N + col;
            if (MODE == 0) {
                float2 vA = make_float2(acc[i][j][0] + b0, acc[i][j][1] + b1);
                float2 vB = make_float2(acc[i][j][2] + b0, acc[i][j][3] + b1);
                *reinterpret_cast<float2*>(pA) = vA;
                *reinterpret_cast<float2*>(pB) = vB;
            } else {
                float2 oA = isFirst ? make_float2(0.f, 0.f)
                                    : *reinterpret_cast<const float2*>(pA);
                float2 oB = isFirst ? make_float2(0.f, 0.f)
                                    : *reinterpret_cast<const float2*>(pB);
                oA.x += gA * (acc[i][j][0] + b0);
                oA.y += gA * (acc[i][j][1] + b1);
                oB.x += gB * (acc[i][j][2] + b0);
                oB.y += gB * (acc[i][j][3] + b1);
                *reinterpret_cast<float2*>(pA) = oA;
                *reinterpret_cast<float2*>(pB) = oB;
            }
        }
    }
}

// ---------------------------------------------------------------------------
// Launch
// ---------------------------------------------------------------------------
extern "C" void kernel_launch(void* const* d_in, const int* in_sizes, int n_in,
                              void* d_out, int out_size) {
    const float* x  = (const float*)d_in[0];
    const float* Wg = (const float*)d_in[1];
    const float* bg = (const float*)d_in[2];
    const float* W1 = (const float*)d_in[3];
    const float* b1 = (const float*)d_in[4];
    const float* W2 = (const float*)d_in[5];
    const float* b2 = (const float*)d_in[6];
    const float* W3 = (const float*)d_in[7];
    const float* b3 = (const float*)d_in[8];
    const float* W4 = (const float*)d_in[9];
    const float* b4 = (const float*)d_in[10];
    const float* W5 = (const float*)d_in[11];
    const float* b5 = (const float*)d_in[12];
    float* out = (float*)d_out;

    void *pWhi, *pWlo, *pxhi, *pxlo, *pAhi, *pAlo, *pC;
    cudaGetSymbolAddress(&pWhi, g_Whi);
    cudaGetSymbolAddress(&pWlo, g_Wlo);
    cudaGetSymbolAddress(&pxhi, g_xhi);
    cudaGetSymbolAddress(&pxlo, g_xlo);
    cudaGetSymbolAddress(&pAhi, g_Ahi);
    cudaGetSymbolAddress(&pAlo, g_Alo);
    cudaGetSymbolAddress(&pC, g_C);
    __nv_bfloat16* Whi = (__nv_bfloat16*)pWhi;
    __nv_bfloat16* Wlo = (__nv_bfloat16*)pWlo;
    __nv_bfloat16* xhi = (__nv_bfloat16*)pxhi;
    __nv_bfloat16* xlo = (__nv_bfloat16*)pxlo;
    __nv_bfloat16* Ahi = (__nv_bfloat16*)pAhi;
    __nv_bfloat16* Alo = (__nv_bfloat16*)pAlo;
    float* Cbuf = (float*)pC;

    cudaFuncSetAttribute(tc_gemm<0>, cudaFuncAttributeMaxDynamicSharedMemorySize, GEMM_SMEM);
    cudaFuncSetAttribute(tc_gemm<1>, cudaFuncAttributeMaxDynamicSharedMemorySize, GEMM_SMEM);

    gate_kernel<<<B_ / 8, 256>>>(x, Wg, bg);
    xconv_kernel<<<(B_ * DIN_ / 4 + 255) / 256, 256>>>(x, xhi, xlo, B_ * DIN_ / 4);

    // Per-expert weight offsets within the packed transposed arrays
    const size_t off1 = 0;
    const size_t off2 = off1 + (size_t)DIN_ * H_;
    const size_t off3 = off2 + (size_t)H_ * H_;
    const size_t off4 = off3 + (size_t)H_ * H_;
    const size_t off5 = off4 + (size_t)H_ * H_;

    const dim3 wblk(32, 8);
    for (int e = 0; e < E_; e++) {
        const size_t eb = (size_t)e * WPE;
        wconv_kernel<<<dim3(H_ / 32, DIN_ / 64), wblk>>>(
            W1 + (size_t)e * DIN_ * H_, Whi + eb + off1, Wlo + eb + off1, DIN_, H_);
        wconv_kernel<<<dim3(H_ / 32, H_ / 64), wblk>>>(
            W2 + (size_t)e * H_ * H_, Whi + eb + off2, Wlo + eb + off2, H_, H_);
        wconv_kernel<<<dim3(H_ / 32, H_ / 64), wblk>>>(
            W3 + (size_t)e * H_ * H_, Whi + eb + off3, Wlo + eb + off3, H_, H_);
        wconv_kernel<<<dim3(H_ / 32, H_ / 64), wblk>>>(
            W4 + (size_t)e * H_ * H_, Whi + eb + off4, Wlo + eb + off4, H_, H_);
        wconv_kernel<<<dim3(DOUT_ / 32, H_ / 64), wblk>>>(
            W5 + (size_t)e * H_ * DOUT_, Whi + eb + off5, Wlo + eb + off5, H_, DOUT_);
    }

    const dim3 gridH(H_ / 128, B_ / 128);
    const dim3 gridO(DOUT_ / 128, B_ / 128);

    for (int e = 0; e < E_; e++) {
        const size_t eb = (size_t)e * WPE;
        const float* b1e = b1 + (size_t)e * H_;
        const float* b2e = b2 + (size_t)e * H_;
        const float* b3e = b3 + (size_t)e * H_;
        const float* b4e = b4 + (size_t)e * H_;
        const float* b5e = b5 + (size_t)e * DOUT_;

        tc_gemm<0><<<gridH, 256, GEMM_SMEM>>>(xhi, xlo, Whi + eb + off1, Wlo + eb + off1,
                                              b1e, Cbuf, H_, DIN_, 0, 0);
        mish_ln_cvt_kernel<<<B_, 256>>>(Cbuf, Ahi, Alo);
        tc_gemm<0><<<gridH, 256, GEMM_SMEM>>>(Ahi, Alo, Whi + eb + off2, Wlo + eb + off2,
                                              b2e, Cbuf, H_, H_, 0, 0);
        mish_ln_cvt_kernel<<<B_, 256>>>(Cbuf, Ahi, Alo);
        tc_gemm<0><<<gridH, 256, GEMM_SMEM>>>(Ahi, Alo, Whi + eb + off3, Wlo + eb + off3,
                                              b3e, Cbuf, H_, H_, 0, 0);
        mish_ln_cvt_kernel<<<B_, 256>>>(Cbuf, Ahi, Alo);
        tc_gemm<0><<<gridH, 256, GEMM_SMEM>>>(Ahi, Alo, Whi + eb + off4, Wlo + eb + off4,
                                              b4e, Cbuf, H_, H_, 0, 0);
        mish_ln_cvt_kernel<<<B_, 256>>>(Cbuf, Ahi, Alo);
        tc_gemm<1><<<gridO, 256, GEMM_SMEM>>>(Ahi, Alo, Whi + eb + off5, Wlo + eb + off5,
                                              b5e, out, DOUT_, H_, e, (e == 0) ? 1 : 0);
    }
}